// round 7
// baseline (speedup 1.0000x reference)
#include <cuda_runtime.h>

// cosine_regularizer: out = (sum(W) - N)/N^2, W = p p^T, p = row-normalized points.
// Identity: sum(W) = || sum_i p_i ||^2  -> one streaming pass + scalar finalize.
// R7: __launch_bounds__(256, 3) lifts the reg budget (was 32 -> loads serialized into
//     small batches). 512-block grid gives only 3.46 CTAs/SM anyway, so a ~80-reg
//     budget costs no occupancy and lets all 8 LDG.128 per warp genuinely batch.

constexpr int N_ROWS = 16384;
constexpr int D      = 256;
constexpr int TPB    = 256;                 // 8 warps
constexpr int WARPS  = TPB / 32;
constexpr int NBLK   = 512;                 // 512*8 warps * 4 rows = 16384 rows
constexpr int ROWS_PER_WARP = 4;
constexpr int NREP   = 16;                  // column-sum replicas (R6 win)

__device__ float        g_rep[NREP][D];   // zero at load; reset by last block each run
__device__ unsigned int g_count;          // zero at load; reset by last block each run

__global__ void __launch_bounds__(TPB, 3)
k_fused(const float* __restrict__ pts, float* __restrict__ out) {
    const int warp = threadIdx.x >> 5;
    const int lane = threadIdx.x & 31;
    const int t    = threadIdx.x;
    const int gw   = blockIdx.x * WARPS + warp;

    // Batch-issue all 8 LDG.128 for this warp's 4 rows (needs ~40 live regs).
    float4 v0[ROWS_PER_WARP], v1[ROWS_PER_WARP];
#pragma unroll
    for (int k = 0; k < ROWS_PER_WARP; k++) {
        const int row = gw + k * (NBLK * WARPS);
        const float4* p = reinterpret_cast<const float4*>(pts) + (size_t)row * (D / 4);
        v0[k] = p[lane];        // cols 4*lane   .. +3
        v1[k] = p[32 + lane];   // cols 128+4*lane .. +3
    }

    // Per-row sum of squares; 4 interleaved warp reductions.
    float ss[ROWS_PER_WARP];
#pragma unroll
    for (int k = 0; k < ROWS_PER_WARP; k++) {
        ss[k] = v0[k].x * v0[k].x + v0[k].y * v0[k].y + v0[k].z * v0[k].z + v0[k].w * v0[k].w
              + v1[k].x * v1[k].x + v1[k].y * v1[k].y + v1[k].z * v1[k].z + v1[k].w * v1[k].w;
    }
#pragma unroll
    for (int off = 16; off > 0; off >>= 1) {
#pragma unroll
        for (int k = 0; k < ROWS_PER_WARP; k++)
            ss[k] += __shfl_xor_sync(0xffffffffu, ss[k], off);
    }

    // rnorm * row into per-lane column accumulators.
    float4 a0 = make_float4(0.f, 0.f, 0.f, 0.f);
    float4 a1 = make_float4(0.f, 0.f, 0.f, 0.f);
#pragma unroll
    for (int k = 0; k < ROWS_PER_WARP; k++) {
        const float rn = rsqrtf(ss[k]);
        a0.x += rn * v0[k].x;  a0.y += rn * v0[k].y;
        a0.z += rn * v0[k].z;  a0.w += rn * v0[k].w;
        a1.x += rn * v1[k].x;  a1.y += rn * v1[k].y;
        a1.z += rn * v1[k].z;  a1.w += rn * v1[k].w;
    }

    // Block-reduce 8 warps' column partials via shared.
    __shared__ float sh[WARPS][D];
    float4* shv = reinterpret_cast<float4*>(sh[warp]);
    shv[lane]      = a0;
    shv[32 + lane] = a1;
    __syncthreads();

    float s = sh[0][t];
#pragma unroll
    for (int w = 1; w < WARPS; w++) s += sh[w][t];

    // Per-column add into this block's replica (32 adds/address chip-wide).
    atomicAdd(&g_rep[blockIdx.x & (NREP - 1)][t], s);

    // ---- last-block detection (release/acquire) ----
    __shared__ unsigned int s_isLast;
    __syncthreads();   // block's adds happen-before t0's release-atom
    if (t == 0) {
        unsigned int old;
        asm volatile("atom.release.gpu.global.add.u32 %0, [%1], 1;"
                     : "=r"(old) : "l"(&g_count) : "memory");
        s_isLast = (old == (unsigned int)(NBLK - 1)) ? 1u : 0u;
    }
    __syncthreads();
    if (!s_isLast) return;

    // Acquire: pairs with all blocks' releases; subsequent L2 reads are coherent.
    if (t == 0) {
        unsigned int dummy;
        asm volatile("atom.acquire.gpu.global.add.u32 %0, [%1], 0;"
                     : "=r"(dummy) : "l"(&g_count) : "memory");
        g_count = 0u;   // reset for next graph replay
    }
    __syncthreads();

    // Fold replicas for this column; reset them for next replay.
    float v = 0.0f;
#pragma unroll
    for (int r = 0; r < NREP; r++) {
        v += __ldcg(&g_rep[r][t]);
        g_rep[r][t] = 0.0f;
    }

    double d = (double)v * (double)v;
#pragma unroll
    for (int off = 16; off > 0; off >>= 1)
        d += __shfl_xor_sync(0xffffffffu, d, off);

    __shared__ double wsum[WARPS];
    if (lane == 0) wsum[warp] = d;
    __syncthreads();
    if (warp == 0) {
        double x = (lane < WARPS) ? wsum[lane] : 0.0;
#pragma unroll
        for (int off = 4; off > 0; off >>= 1)
            x += __shfl_xor_sync(0xffffffffu, x, off);
        if (lane == 0) {
            const double n = (double)N_ROWS;
            out[0] = (float)((x - n) / (n * n));
        }
    }
}

extern "C" void kernel_launch(void* const* d_in, const int* in_sizes, int n_in,
                              void* d_out, int out_size) {
    const float* pts = (const float*)d_in[0];
    (void)in_sizes; (void)n_in; (void)out_size;
    k_fused<<<NBLK, TPB>>>(pts, (float*)d_out);
}